// round 11
// baseline (speedup 1.0000x reference)
#include <cuda_runtime.h>
#include <math_constants.h>

// kNN graph = cell-sort (spatial locality) + R6 dense scan with a seeded
// threshold. PyG knn_graph(loop=False): B=16 x n=4096, D=3, k=16.
// Output (float32 flat): [nbr_global | centers | topk_d2], each total_n*K.

#define K     16
#define KP1   17
#define NPER  4096
#define TPB   256
#define CPG   (NPER / TPB)
#define NG    16
#define G     18
#define GC    (G * G * G)        // 5832
#define GCP   5888               // 256*23, padded for the block scan
#define LO    (-4.5f)
#define HCELL 0.5f

#define PB      12               // FIFO slots: flush keeps cnt<=4, +8 pushes = 12
#define SLOT_B  (TPB * 8u)       // 2048 B between a thread's FIFO slots
#define FLUSH_B (5u * SLOT_B)    // flush when cnt >= 5
#define INIT_KEY 0xFFFFFFFFFFFFFFFFull

// smem byte offsets (query kernel)
#define SM_SX    0
#define SM_SY    16384
#define SM_SZ    32768
#define SM_SS    49152
#define SM_SIDX  65536                       // u16[4096]    8192
#define SM_PEND  (65536 + 8192)              // u64[PB][256] 24576
#define SM_TOTAL (65536 + 8192 + 24576)      // 98304 (2 CTA/SM ok)

__device__ float          g_sx  [NG][NPER];
__device__ float          g_sy  [NG][NPER];
__device__ float          g_sz  [NG][NPER];
__device__ float          g_ss  [NG][NPER];
__device__ unsigned short g_sidx[NG][NPER];  // sorted slot -> original idx

__device__ __forceinline__ int cellCoord(float v) {
    int c = (int)floorf((v - LO) * (1.0f / HCELL));
    return min(G - 1, max(0, c));
}

#define FMA_F32X2(out, a, b, c) \
    asm("fma.rn.f32x2 %0, %1, %2, %3;" : "=l"(out) : "l"(a), "l"(b), "l"(c))
#define MUL_F32X2_(out, a, b) \
    asm("mul.rn.f32x2 %0, %1, %2;" : "=l"(out) : "l"(a), "l"(b))
#define ADD_F32X2_(out, a, b) \
    asm("add.rn.f32x2 %0, %1, %2;" : "=l"(out) : "l"(a), "l"(b))
#define PACK2(out, lo, hi) \
    asm("mov.b64 %0, {%1, %2};" : "=l"(out) : "r"(lo), "r"(hi))
#define UNPACK2(lo, hi, in) \
    asm("mov.b64 {%0, %1}, %2;" : "=r"(lo), "=r"(hi) : "l"(in))

// Branchless predicated push (R6-validated): setp.le guards the store and
// (via selp) yields the {0, SLOT_B} offset increment. No BSSY/BSYNC.
#define PUSHB(dv, jv)                                                         \
    do {                                                                      \
        unsigned long long kk_;                                               \
        asm("mov.b64 %0, {%1, %2};"                                           \
            : "=l"(kk_) : "r"((unsigned)(jv)), "r"(__float_as_uint(dv)));     \
        unsigned inc_;                                                        \
        asm volatile(                                                         \
            "{\n\t.reg .pred p;\n\t"                                          \
            "setp.le.f32 p, %1, %2;\n\t"                                      \
            "selp.u32 %0, %3, 0, p;\n\t"                                      \
            "@p st.shared.b64 [%4], %5;\n\t}"                                 \
            : "=r"(inc_)                                                      \
            : "f"(dv), "f"(worstf), "n"(SLOT_B),                              \
              "r"(pbase + offb), "l"(kk_)                                     \
            : "memory");                                                      \
        offb += inc_;                                                         \
    } while (0)

// Drain FIFO into the sorted K+1 u64-key list; key = (monotone dist bits,
// ORIGINAL idx) = jax.lax.top_k's exact (value, lower-index) order.
// fminf(list17th, cap): while the list still holds INIT keys the decoded
// value is NaN and fminf returns cap (valid upper bound), afterwards the
// list's 17th is <= cap anyway.
#define DRAIN()                                                               \
    {                                                                         \
        const int cnt_ = (int)(offb >> 11);                                   \
        offb = 0;                                                             \
        const unsigned long long* myp_ = pend + tid;                          \
        _Pragma("unroll 1")                                                   \
        for (int p_ = 0; p_ < cnt_; ++p_) {                                   \
            const unsigned long long kk_ = myp_[(size_t)p_ * TPB];            \
            unsigned lo_, hi_;                                                \
            UNPACK2(lo_, hi_, kk_);                                           \
            hi_ ^= ((unsigned)(((int)hi_) >> 31)) | 0x80000000u;              \
            unsigned long long key_ =                                         \
                ((unsigned long long)hi_ << 32) | (unsigned)sidx[lo_];        \
            if (key_ < bk[KP1 - 1]) {                                         \
                _Pragma("unroll")                                             \
                for (int m_ = 0; m_ < KP1; ++m_) {                            \
                    const bool sw_ = key_ < bk[m_];                           \
                    const unsigned long long l2_ = sw_ ? key_ : bk[m_];       \
                    key_   = sw_ ? bk[m_] : key_;                             \
                    bk[m_] = l2_;                                             \
                }                                                             \
            }                                                                 \
        }                                                                     \
        const unsigned wh_ = (unsigned)(bk[KP1 - 1] >> 32);                   \
        const unsigned wu_ = (wh_ & 0x80000000u) ? (wh_ ^ 0x80000000u) : ~wh_;\
        worstf = fminf(__uint_as_float(wu_), cap);                            \
    }

// ---------------------------------------------------------------- build ----
__global__ __launch_bounds__(TPB, 1)
void knn_build_kernel(const float* __restrict__ pos)
{
    __shared__ int cnt[GCP];
    __shared__ int partial[TPB];
    const int g = blockIdx.x, tid = threadIdx.x, base = g * NPER;
    const float* gp = pos + (size_t)base * 3;

    for (int i = tid; i < GCP; i += TPB) cnt[i] = 0;
    __syncthreads();

    for (int p = tid; p < NPER; p += TPB) {
        const float x = gp[3 * p], y = gp[3 * p + 1], z = gp[3 * p + 2];
        atomicAdd(&cnt[(cellCoord(z) * G + cellCoord(y)) * G + cellCoord(x)], 1);
    }
    __syncthreads();

    const int c0 = tid * 23;
    int s = 0;
    for (int i = 0; i < 23; ++i) s += cnt[c0 + i];
    partial[tid] = s;
    __syncthreads();
    if (tid == 0) {
        int run = 0;
        for (int t = 0; t < TPB; ++t) { const int v = partial[t]; partial[t] = run; run += v; }
    }
    __syncthreads();
    int run = partial[tid];
    for (int i = 0; i < 23; ++i) { const int v = cnt[c0 + i]; cnt[c0 + i] = run; run += v; }
    __syncthreads();

    // scatter into sorted SoA; norm op order matches the query dot chain so
    // the self-distance evaluates to exactly +0.
    for (int p = tid; p < NPER; p += TPB) {
        const float x = gp[3 * p], y = gp[3 * p + 1], z = gp[3 * p + 2];
        const int id = (cellCoord(z) * G + cellCoord(y)) * G + cellCoord(x);
        const int slot = atomicAdd(&cnt[id], 1);
        g_sx[g][slot] = x; g_sy[g][slot] = y; g_sz[g][slot] = z;
        g_ss[g][slot] = fmaf(z, z, fmaf(y, y, x * x));
        g_sidx[g][slot] = (unsigned short)p;
    }
}

// ---------------------------------------------------------------- query ----
__global__ __launch_bounds__(TPB, 2)
void knn_query_kernel(float* __restrict__ out, int total_n)
{
    extern __shared__ char smraw[];
    float* sx = (float*)(smraw + SM_SX);
    float* sy = (float*)(smraw + SM_SY);
    float* sz = (float*)(smraw + SM_SZ);
    float* ss = (float*)(smraw + SM_SS);
    unsigned short*     sidx = (unsigned short*)(smraw + SM_SIDX);
    unsigned long long* pend = (unsigned long long*)(smraw + SM_PEND);

    const int graph = blockIdx.x / CPG;
    const int base  = graph * NPER;
    const int tid   = threadIdx.x;

    for (int p = tid; p < NPER; p += TPB) {
        sx[p] = g_sx[graph][p];
        sy[p] = g_sy[graph][p];
        sz[p] = g_sz[graph][p];
        ss[p] = g_ss[graph][p];
        sidx[p] = g_sidx[graph][p];
    }
    __syncthreads();

    const int   s  = (blockIdx.x % CPG) * TPB + tid;   // this lane's sorted slot
    const float qx = sx[s], qy = sy[s], qz = sz[s], qs = ss[s];
    const int   qi = (int)sidx[s];                     // original local idx

    // ---- seed cap: 17th-smallest distance over the 64 sorted-order slots
    // around s (spatially local after cell sort). Subset 17th >= true 17th,
    // so cap is a valid upper bound for the push filter.
    float cap;
    {
        int w0 = s - 32;
        w0 = max(w0, 0);
        w0 = min(w0, NPER - 64);
        float sd[KP1];
#pragma unroll
        for (int m = 0; m < KP1; ++m) sd[m] = CUDART_INF_F;
#pragma unroll 1
        for (int i = 0; i < 64; ++i) {
            const int j = w0 + i;
            const float dot = fmaf(qz, sz[j], fmaf(qy, sy[j], qx * sx[j]));
            float d = fmaf(-2.f, dot, qs + ss[j]);   // reference op order
            if (d < sd[KP1 - 1]) {
#pragma unroll
                for (int m = 0; m < KP1; ++m) {
                    const float mn_ = fminf(d, sd[m]);
                    const float mx_ = fmaxf(d, sd[m]);
                    sd[m] = mn_; d = mx_;
                }
            }
        }
        cap = sd[KP1 - 1];
    }

    unsigned long long bk[KP1];
#pragma unroll
    for (int m = 0; m < KP1; ++m) bk[m] = INIT_KEY;
    float worstf = cap;

    unsigned long long qx2, qy2, qz2, qs2, m2;
    {
        const unsigned xb = __float_as_uint(qx), yb = __float_as_uint(qy);
        const unsigned zb = __float_as_uint(qz), sb = __float_as_uint(qs);
        const unsigned nb = __float_as_uint(-2.0f);
        PACK2(qx2, xb, xb); PACK2(qy2, yb, yb); PACK2(qz2, zb, zb);
        PACK2(qs2, sb, sb); PACK2(m2, nb, nb);
    }

    unsigned offb = 0;
    const unsigned pbase = (unsigned)__cvta_generic_to_shared(pend + tid);

#pragma unroll 2
    for (int j0 = 0; j0 < NPER; j0 += 8) {
        const ulonglong2 Xa = *reinterpret_cast<const ulonglong2*>(sx + j0);
        const ulonglong2 Ya = *reinterpret_cast<const ulonglong2*>(sy + j0);
        const ulonglong2 Za = *reinterpret_cast<const ulonglong2*>(sz + j0);
        const ulonglong2 Sa = *reinterpret_cast<const ulonglong2*>(ss + j0);
        const ulonglong2 Xb = *reinterpret_cast<const ulonglong2*>(sx + j0 + 4);
        const ulonglong2 Yb = *reinterpret_cast<const ulonglong2*>(sy + j0 + 4);
        const ulonglong2 Zb = *reinterpret_cast<const ulonglong2*>(sz + j0 + 4);
        const ulonglong2 Sb = *reinterpret_cast<const ulonglong2*>(ss + j0 + 4);

        // d = (qs + s) - 2*dot; f32x2 = two independent fp32 FMAs with the
        // exact op order/rounding of the scalar reference formula.
        unsigned long long dt, tt, dp0, dp1, dp2, dp3;
        MUL_F32X2_(dt, qx2, Xa.x); FMA_F32X2(dt, qy2, Ya.x, dt); FMA_F32X2(dt, qz2, Za.x, dt);
        ADD_F32X2_(tt, Sa.x, qs2); FMA_F32X2(dp0, m2, dt, tt);
        MUL_F32X2_(dt, qx2, Xa.y); FMA_F32X2(dt, qy2, Ya.y, dt); FMA_F32X2(dt, qz2, Za.y, dt);
        ADD_F32X2_(tt, Sa.y, qs2); FMA_F32X2(dp1, m2, dt, tt);
        MUL_F32X2_(dt, qx2, Xb.x); FMA_F32X2(dt, qy2, Yb.x, dt); FMA_F32X2(dt, qz2, Zb.x, dt);
        ADD_F32X2_(tt, Sb.x, qs2); FMA_F32X2(dp2, m2, dt, tt);
        MUL_F32X2_(dt, qx2, Xb.y); FMA_F32X2(dt, qy2, Yb.y, dt); FMA_F32X2(dt, qz2, Zb.y, dt);
        ADD_F32X2_(tt, Sb.y, qs2); FMA_F32X2(dp3, m2, dt, tt);

        unsigned u0, u1, u2, u3, u4, u5, u6, u7;
        UNPACK2(u0, u1, dp0); UNPACK2(u2, u3, dp1);
        UNPACK2(u4, u5, dp2); UNPACK2(u6, u7, dp3);

        PUSHB(__uint_as_float(u0), j0 + 0);
        PUSHB(__uint_as_float(u1), j0 + 1);
        PUSHB(__uint_as_float(u2), j0 + 2);
        PUSHB(__uint_as_float(u3), j0 + 3);
        PUSHB(__uint_as_float(u4), j0 + 4);
        PUSHB(__uint_as_float(u5), j0 + 5);
        PUSHB(__uint_as_float(u6), j0 + 6);
        PUSHB(__uint_as_float(u7), j0 + 7);

        if (__any_sync(0xFFFFFFFFu, offb >= FLUSH_B)) DRAIN();
    }

    DRAIN();

    // Emit: drop the single self entry (orig idx == qi, d == +0), keep K.
    const int    gq = base + qi;
    const size_t Nk = (size_t)total_n * K;
    int w = 0;
#pragma unroll
    for (int m = 0; m < KP1; ++m) {
        const int      idx = (int)(unsigned)bk[m];
        const unsigned hi  = (unsigned)(bk[m] >> 32);
        const unsigned du  = (hi & 0x80000000u) ? (hi ^ 0x80000000u) : ~hi;
        if (idx != qi && w < K) {
            const size_t e = (size_t)gq * K + w;
            out[e]          = (float)(idx + base);
            out[Nk + e]     = (float)gq;
            out[2 * Nk + e] = __uint_as_float(du);
            ++w;
        }
    }
}

extern "C" void kernel_launch(void* const* d_in, const int* in_sizes, int n_in,
                              void* d_out, int out_size)
{
    const float* pos = (const float*)d_in[0];
    const int total_n = in_sizes[0] / 3;
    const int ngraphs = total_n / NPER;

    knn_build_kernel<<<ngraphs, TPB>>>(pos);

    cudaFuncSetAttribute(knn_query_kernel,
                         cudaFuncAttributeMaxDynamicSharedMemorySize, SM_TOTAL);
    knn_query_kernel<<<ngraphs * CPG, TPB, SM_TOTAL>>>((float*)d_out, total_n);
}

// round 12
// speedup vs baseline: 2.0103x; 2.0103x over previous
#include <cuda_runtime.h>
#include <math_constants.h>

// Exact kNN graph via z-sorted interval growth + the R6 dense 8-wide engine.
// PyG knn_graph(loop=False): B=16 x n=4096, D=3, k=16.
// Output (float32 flat): [nbr_global | centers | topk_d2], each total_n*K.

#define K     16
#define KP1   17
#define NPER  4096
#define TPB   256
#define CPG   (NPER / TPB)
#define NG    16
#define NB    256               // z bins
#define ZLO   (-4.5f)
#define HB    (9.0f / 256.0f)
#define INVHB (256.0f / 9.0f)

#define PB      12
#define SLOT_B  (TPB * 8u)
#define FLUSH_B (5u * SLOT_B)
#define INIT_KEY 0xFFFFFFFFFFFFFFFFull

// smem byte offsets (query kernel)
#define SM_SX    0
#define SM_SY    16384
#define SM_SZ    32768
#define SM_SS    49152
#define SM_SIDX  65536                       // u16[4096]    8192
#define SM_PEND  (65536 + 8192)              // u64[PB][256] 24576
#define SM_SBIN  (65536 + 8192 + 24576)      // u16[NB+1]    514 (pad 1024)
#define SM_TOTAL (65536 + 8192 + 24576 + 1024)

__device__ float          g_sx  [NG][NPER];
__device__ float          g_sy  [NG][NPER];
__device__ float          g_sz  [NG][NPER];
__device__ float          g_ss  [NG][NPER];
__device__ unsigned short g_sidx[NG][NPER];   // sorted slot -> original idx
__device__ unsigned short g_sbin[NG][NB + 1]; // cumulative bin starts

__device__ __forceinline__ int zbin(float z) {
    int b = (int)floorf((z - ZLO) * INVHB);
    return min(NB - 1, max(0, b));
}

#define FMA_F32X2(out, a, b, c) \
    asm("fma.rn.f32x2 %0, %1, %2, %3;" : "=l"(out) : "l"(a), "l"(b), "l"(c))
#define MUL_F32X2_(out, a, b) \
    asm("mul.rn.f32x2 %0, %1, %2;" : "=l"(out) : "l"(a), "l"(b))
#define ADD_F32X2_(out, a, b) \
    asm("add.rn.f32x2 %0, %1, %2;" : "=l"(out) : "l"(a), "l"(b))
#define PACK2(out, lo, hi) \
    asm("mov.b64 %0, {%1, %2};" : "=l"(out) : "r"(lo), "r"(hi))
#define UNPACK2(lo, hi, in) \
    asm("mov.b64 {%0, %1}, %2;" : "=r"(lo), "=r"(hi) : "l"(in))

// Branchless predicated push (R6-validated).
#define PUSHB(dv, jv)                                                         \
    do {                                                                      \
        unsigned long long kk_;                                               \
        asm("mov.b64 %0, {%1, %2};"                                           \
            : "=l"(kk_) : "r"((unsigned)(jv)), "r"(__float_as_uint(dv)));     \
        unsigned inc_;                                                        \
        asm volatile(                                                         \
            "{\n\t.reg .pred p;\n\t"                                          \
            "setp.le.f32 p, %1, %2;\n\t"                                      \
            "selp.u32 %0, %3, 0, p;\n\t"                                      \
            "@p st.shared.b64 [%4], %5;\n\t}"                                 \
            : "=r"(inc_)                                                      \
            : "f"(dv), "f"(worstf), "n"(SLOT_B),                              \
              "r"(pbase + offb), "l"(kk_)                                     \
            : "memory");                                                      \
        offb += inc_;                                                         \
    } while (0)

// Drain FIFO into the sorted K+1 u64-key list; key = (monotone dist bits,
// ORIGINAL idx) = jax.lax.top_k's exact (value, lower-index) order.
#define DRAIN()                                                               \
    {                                                                         \
        const int cnt_ = (int)(offb >> 11);                                   \
        offb = 0;                                                             \
        const unsigned long long* myp_ = pend + tid;                          \
        _Pragma("unroll 1")                                                   \
        for (int p_ = 0; p_ < cnt_; ++p_) {                                   \
            const unsigned long long kk_ = myp_[(size_t)p_ * TPB];            \
            unsigned lo_, hi_;                                                \
            UNPACK2(lo_, hi_, kk_);                                           \
            hi_ ^= ((unsigned)(((int)hi_) >> 31)) | 0x80000000u;              \
            unsigned long long key_ =                                         \
                ((unsigned long long)hi_ << 32) | (unsigned)sidx[lo_];        \
            if (key_ < bk[KP1 - 1]) {                                         \
                _Pragma("unroll")                                             \
                for (int m_ = 0; m_ < KP1; ++m_) {                            \
                    const bool sw_ = key_ < bk[m_];                           \
                    const unsigned long long l2_ = sw_ ? key_ : bk[m_];       \
                    key_   = sw_ ? bk[m_] : key_;                             \
                    bk[m_] = l2_;                                             \
                }                                                             \
            }                                                                 \
        }                                                                     \
        const unsigned wh_ = (unsigned)(bk[KP1 - 1] >> 32);                   \
        const unsigned wu_ = (wh_ & 0x80000000u) ? (wh_ ^ 0x80000000u) : ~wh_;\
        worstf = fminf(__uint_as_float(wu_), worstf);                         \
    }

// R6 dense 8-wide scan over an 8-aligned uniform slot range [a_, b_).
#define SCAN_RANGE(a_, b_)                                                    \
    for (int j0 = (a_); j0 < (b_); j0 += 8) {                                 \
        const ulonglong2 Xa = *(const ulonglong2*)(sx + j0);                  \
        const ulonglong2 Ya = *(const ulonglong2*)(sy + j0);                  \
        const ulonglong2 Za = *(const ulonglong2*)(sz + j0);                  \
        const ulonglong2 Sa = *(const ulonglong2*)(ss + j0);                  \
        const ulonglong2 Xb = *(const ulonglong2*)(sx + j0 + 4);              \
        const ulonglong2 Yb = *(const ulonglong2*)(sy + j0 + 4);              \
        const ulonglong2 Zb = *(const ulonglong2*)(sz + j0 + 4);              \
        const ulonglong2 Sb = *(const ulonglong2*)(ss + j0 + 4);              \
        unsigned long long dt, tt, dp0, dp1, dp2, dp3;                        \
        MUL_F32X2_(dt, qx2, Xa.x); FMA_F32X2(dt, qy2, Ya.x, dt);              \
        FMA_F32X2(dt, qz2, Za.x, dt);                                         \
        ADD_F32X2_(tt, Sa.x, qs2); FMA_F32X2(dp0, m2, dt, tt);                \
        MUL_F32X2_(dt, qx2, Xa.y); FMA_F32X2(dt, qy2, Ya.y, dt);              \
        FMA_F32X2(dt, qz2, Za.y, dt);                                         \
        ADD_F32X2_(tt, Sa.y, qs2); FMA_F32X2(dp1, m2, dt, tt);                \
        MUL_F32X2_(dt, qx2, Xb.x); FMA_F32X2(dt, qy2, Yb.x, dt);              \
        FMA_F32X2(dt, qz2, Zb.x, dt);                                         \
        ADD_F32X2_(tt, Sb.x, qs2); FMA_F32X2(dp2, m2, dt, tt);                \
        MUL_F32X2_(dt, qx2, Xb.y); FMA_F32X2(dt, qy2, Yb.y, dt);              \
        FMA_F32X2(dt, qz2, Zb.y, dt);                                         \
        ADD_F32X2_(tt, Sb.y, qs2); FMA_F32X2(dp3, m2, dt, tt);                \
        unsigned u0, u1, u2, u3, u4, u5, u6, u7;                              \
        UNPACK2(u0, u1, dp0); UNPACK2(u2, u3, dp1);                           \
        UNPACK2(u4, u5, dp2); UNPACK2(u6, u7, dp3);                           \
        PUSHB(__uint_as_float(u0), j0 + 0);                                   \
        PUSHB(__uint_as_float(u1), j0 + 1);                                   \
        PUSHB(__uint_as_float(u2), j0 + 2);                                   \
        PUSHB(__uint_as_float(u3), j0 + 3);                                   \
        PUSHB(__uint_as_float(u4), j0 + 4);                                   \
        PUSHB(__uint_as_float(u5), j0 + 5);                                   \
        PUSHB(__uint_as_float(u6), j0 + 6);                                   \
        PUSHB(__uint_as_float(u7), j0 + 7);                                   \
        if (__any_sync(0xFFFFFFFFu, offb >= FLUSH_B)) DRAIN();                \
    }

// ---------------------------------------------------------------- build ----
__global__ __launch_bounds__(TPB, 1)
void knn_build_kernel(const float* __restrict__ pos)
{
    __shared__ int cnt[NB + 1];
    const int g = blockIdx.x, tid = threadIdx.x, base = g * NPER;
    const float* gp = pos + (size_t)base * 3;

    if (tid <= NB) cnt[tid] = 0;
    __syncthreads();

    for (int p = tid; p < NPER; p += TPB)
        atomicAdd(&cnt[zbin(gp[3 * p + 2])], 1);
    __syncthreads();

    if (tid == 0) {
        int run = 0;
        for (int i = 0; i < NB; ++i) { const int v = cnt[i]; cnt[i] = run; run += v; }
        cnt[NB] = run;
    }
    __syncthreads();

    if (tid <= NB) g_sbin[g][tid] = (unsigned short)cnt[tid];
    __syncthreads();

    // scatter into z-sorted SoA; norm op order matches the query dot chain
    // so the self-distance evaluates to exactly +0.
    for (int p = tid; p < NPER; p += TPB) {
        const float x = gp[3 * p], y = gp[3 * p + 1], z = gp[3 * p + 2];
        const int slot = atomicAdd(&cnt[zbin(z)], 1);
        g_sx[g][slot] = x; g_sy[g][slot] = y; g_sz[g][slot] = z;
        g_ss[g][slot] = fmaf(z, z, fmaf(y, y, x * x));
        g_sidx[g][slot] = (unsigned short)p;
    }
}

// ---------------------------------------------------------------- query ----
__global__ __launch_bounds__(TPB, 2)
void knn_query_kernel(float* __restrict__ out, int total_n)
{
    extern __shared__ char smraw[];
    float* sx = (float*)(smraw + SM_SX);
    float* sy = (float*)(smraw + SM_SY);
    float* sz = (float*)(smraw + SM_SZ);
    float* ss = (float*)(smraw + SM_SS);
    unsigned short*     sidx = (unsigned short*)(smraw + SM_SIDX);
    unsigned long long* pend = (unsigned long long*)(smraw + SM_PEND);
    unsigned short*     sbin = (unsigned short*)(smraw + SM_SBIN);

    const int graph = blockIdx.x / CPG;
    const int base  = graph * NPER;
    const int tid   = threadIdx.x;

    for (int p = tid; p < NPER; p += TPB) {
        sx[p] = g_sx[graph][p];
        sy[p] = g_sy[graph][p];
        sz[p] = g_sz[graph][p];
        ss[p] = g_ss[graph][p];
        sidx[p] = g_sidx[graph][p];
    }
    if (tid <= NB) sbin[tid] = g_sbin[graph][tid];
    __syncthreads();

    const int   c0 = (blockIdx.x % CPG) * TPB;         // CTA's sorted range
    const int   s  = c0 + tid;
    const float qx = sx[s], qy = sy[s], qz = sz[s], qs = ss[s];
    const int   qi = (int)sidx[s];

    unsigned long long bk[KP1];
#pragma unroll
    for (int m = 0; m < KP1; ++m) bk[m] = INIT_KEY;
    float worstf = CUDART_INF_F;

    unsigned long long qx2, qy2, qz2, qs2, m2;
    {
        const unsigned xb = __float_as_uint(qx), yb = __float_as_uint(qy);
        const unsigned zb = __float_as_uint(qz), sb = __float_as_uint(qs);
        const unsigned nb = __float_as_uint(-2.0f);
        PACK2(qx2, xb, xb); PACK2(qy2, yb, yb); PACK2(qz2, zb, zb);
        PACK2(qs2, sb, sb); PACK2(m2, nb, nb);
    }

    unsigned offb = 0;
    const unsigned pbase = (unsigned)__cvta_generic_to_shared(pend + tid);

    // Initial scan: the CTA's own 256 slots (nearest in z -> fast converge).
    SCAN_RANGE(c0, c0 + TPB);

    int slo = c0, shi = c0 + TPB;
    const float zc = sz[c0 + 128];   // uniform CTA center z

    while (true) {
        DRAIN();

        // Per-lane stop bound: unscanned left points have z <= right edge of
        // the bin containing slot slo-1; right ones have z >= left edge of
        // the bin containing slot shi. d >= (delta z)^2.
        float gapL = CUDART_INF_F, gapR = CUDART_INF_F;
        float eL = 0.0f, eR = 0.0f;
        if (slo > 0) {
            eL = ZLO + (float)(zbin(sz[slo - 1]) + 1) * HB;
            gapL = qz - eL;
        }
        if (shi < NPER) {
            eR = ZLO + (float)zbin(sz[shi]) * HB;
            gapR = eR - qz;
        }
        float gmin = fmaxf(fminf(gapL, gapR), 0.0f);
        const int notdone = !((worstf + 1e-4f) <= 0.999f * gmin * gmin);
        if (!__syncthreads_or(notdone)) break;
        if (slo == 0 && shi == NPER) break;   // everything scanned

        // Uniform side choice: extend toward the nearer unscanned edge.
        bool goLeft;
        if (slo == 0)          goLeft = false;
        else if (shi == NPER)  goLeft = true;
        else                   goLeft = (zc - eL) <= (eR - zc);

        if (goLeft) {
            const int nlo = max(slo - 32, 0);
            SCAN_RANGE(nlo, slo);
            slo = nlo;
        } else {
            const int nhi = min(shi + 32, NPER);
            SCAN_RANGE(shi, nhi);
            shi = nhi;
        }
    }

    // Emit: drop the single self entry (orig idx == qi, d == +0), keep K.
    const int    gq = base + qi;
    const size_t Nk = (size_t)total_n * K;
    int w = 0;
#pragma unroll
    for (int m = 0; m < KP1; ++m) {
        const int      idx = (int)(unsigned)bk[m];
        const unsigned hi  = (unsigned)(bk[m] >> 32);
        const unsigned du  = (hi & 0x80000000u) ? (hi ^ 0x80000000u) : ~hi;
        if (idx != qi && w < K) {
            const size_t e = (size_t)gq * K + w;
            out[e]          = (float)(idx + base);
            out[Nk + e]     = (float)gq;
            out[2 * Nk + e] = __uint_as_float(du);
            ++w;
        }
    }
}

extern "C" void kernel_launch(void* const* d_in, const int* in_sizes, int n_in,
                              void* d_out, int out_size)
{
    const float* pos = (const float*)d_in[0];
    const int total_n = in_sizes[0] / 3;
    const int ngraphs = total_n / NPER;

    knn_build_kernel<<<ngraphs, TPB>>>(pos);

    cudaFuncSetAttribute(knn_query_kernel,
                         cudaFuncAttributeMaxDynamicSharedMemorySize, SM_TOTAL);
    knn_query_kernel<<<ngraphs * CPG, TPB, SM_TOTAL>>>((float*)d_out, total_n);
}